// round 13
// baseline (speedup 1.0000x reference)
#include <cuda_runtime.h>
#include <cuda_fp16.h>
#include <math.h>
#include <stdint.h>

#define NW     4096
#define WLEN   16
#define GD     300
#define CE     50
#define CH     128
#define G4     512
#define CV     100
#define HID    512
#define FEAT   428

#define MW     32                 // words per CTA (MMA M)
#define THR    512                // 16 warps, each owns 32 gate columns
#define NBLK   (NW / MW)          // 128
#define KC     128                // recurrent K only (emb folded into cgq gather)
#define KATOMS (KC / 16)          // 8
#define ROWB   272                // smem row stride bytes (256B data + 16B pad)
#define ABYTES (MW * ROWB)        // 8704

// ---- smem layout (double-buffered A; total 157312) ----
#define SM_CI8   0                          // 32*16 u8 = 512
#define SM_A0    640                        // 8704
#define SM_A1    (SM_A0 + ABYTES)           // 9344
#define SM_B     (SM_A1 + ABYTES)           // 18048; 512*272 = 139264
#define SM_TOTAL (SM_B + G4 * ROWB)         // 157312

// ---- device scratch ----
__device__ __align__(16) __half g_Bq[G4 * KC];      // W_hh fp16, permuted rows
__device__ __align__(16) __half g_cgq[CV * G4];     // per-char gates fp16, permuted cols
__device__ float g_gsum[GD];
__device__ float g_hsum[CH];
__device__ float g_out2[2];
__device__ int   g_t2 = 0;

// ---- helpers ----
__device__ __forceinline__ uint32_t smem_u32(const void* p) {
    uint32_t a;
    asm("{ .reg .u64 t; cvta.to.shared.u64 t, %1; cvt.u32.u64 %0, t; }" : "=r"(a) : "l"(p));
    return a;
}
__device__ __forceinline__ void ldsm4(uint32_t addr, uint32_t r[4]) {
    asm volatile("ldmatrix.sync.aligned.m8n8.x4.shared.b16 {%0,%1,%2,%3}, [%4];"
        : "=r"(r[0]), "=r"(r[1]), "=r"(r[2]), "=r"(r[3]) : "r"(addr));
}
__device__ __forceinline__ void mma16816(float d[4], const uint32_t a[4], const uint32_t b[2]) {
    asm volatile("mma.sync.aligned.m16n8k16.row.col.f32.f16.f16.f32 "
        "{%0,%1,%2,%3}, {%4,%5,%6,%7}, {%8,%9}, {%0,%1,%2,%3};"
        : "+f"(d[0]), "+f"(d[1]), "+f"(d[2]), "+f"(d[3])
        : "r"(a[0]), "r"(a[1]), "r"(a[2]), "r"(a[3]), "r"(b[0]), "r"(b[1]));
}
__device__ __forceinline__ float tanha(float x) {
    float y; asm("tanh.approx.f32 %0, %1;" : "=f"(y) : "f"(x)); return y;
}
__device__ __forceinline__ float ldcv(const float* p) {
    float v; asm volatile("ld.global.cv.f32 %0, [%1];" : "=f"(v) : "l"(p)); return v;
}

// gate-column permutation: warp w owns cols j = w*32 + c, c = a*8 + q*2 + e
//   gate g = 2*(a>>1) + e ; unit u = w*8 + (a&1)*4 + q

// ---------------------------------------------------------------------------
// Prep: blocks 0..511 -> g_Bq rows; 512..611 -> cgq per char; 612 -> zeros.
// grid 613 x 128
// ---------------------------------------------------------------------------
__global__ void prep_all(const float* __restrict__ W_hh, const float* __restrict__ W_ih,
                         const float* __restrict__ b_ih, const float* __restrict__ b_hh,
                         const float* __restrict__ char_embed) {
    if (blockIdx.x < G4) {
        int j = blockIdx.x;
        int w = j >> 5, c = j & 31;
        int a = c >> 3, q = (c >> 1) & 3, e = c & 1;
        int g = 2 * (a >> 1) + e;
        int u = w * 8 + (a & 1) * 4 + q;
        int row = g * CH + u;
        int k = threadIdx.x;                 // 0..127
        g_Bq[j * KC + k] = __float2half(W_hh[row * CH + k]);
    } else if (blockIdx.x < G4 + CV) {
        __shared__ float ce[CE];
        int cix = blockIdx.x - G4;
        if (threadIdx.x < CE) ce[threadIdx.x] = char_embed[cix * CE + threadIdx.x];
        __syncthreads();
#pragma unroll
        for (int rep = 0; rep < 4; rep++) {
            int j = rep * 128 + threadIdx.x;
            int w = j >> 5, c = j & 31;
            int a = c >> 3, q = (c >> 1) & 3, e = c & 1;
            int g = 2 * (a >> 1) + e;
            int u = w * 8 + (a & 1) * 4 + q;
            int row = g * CH + u;
            float acc = b_ih[row] + b_hh[row];
            const float* wv = W_ih + row * CE;
#pragma unroll
            for (int k = 0; k < CE; k++) acc = fmaf(wv[k], ce[k], acc);
            g_cgq[cix * G4 + j] = __float2half(acc);
        }
    } else {
        for (int i = threadIdx.x; i < GD + CH; i += 128) {
            if (i < GD) g_gsum[i] = 0.f;
            else        g_hsum[i - GD] = 0.f;
        }
        if (threadIdx.x == 0) { g_out2[0] = 0.f; g_out2[1] = 0.f; g_t2 = 0; }
    }
}

// ---------------------------------------------------------------------------
// LSTM via mma.sync + fused glove gather; K=128; per-char gates added in
// epilogue from fp16 cgq table. Double-buffered A, 1 barrier/step.
// 128 CTAs x 512 thr; M=32 words, N=512 gates.
// ---------------------------------------------------------------------------
__global__ void __launch_bounds__(THR, 1) lstm_mma_kernel(const int* __restrict__ cidx,
                                                          const int* __restrict__ widx,
                                                          const float* __restrict__ glove) {
    extern __shared__ unsigned char sm[];
    uint32_t smb = smem_u32(sm);
    int tid = threadIdx.x;
    int w = tid >> 5, lane = tid & 31;
    int q = lane & 3, r = lane >> 2;

    const int wb = blockIdx.x * MW;
    sm[SM_CI8 + tid] = (unsigned char)cidx[wb * WLEN + tid];   // 512 = MW*WLEN
    // zero A0 (h starts at 0): 544 uint4
    for (int i = tid; i < ABYTES / 16; i += THR)
        ((uint4*)(sm + SM_A0))[i] = make_uint4(0, 0, 0, 0);
    // stream B (512 rows x 16 uint4)
    for (int i = tid; i < G4 * 16; i += THR) {
        int row = i >> 4, s = i & 15;
        *(uint4*)(sm + SM_B + row * ROWB + s * 16) =
            *(const uint4*)((const unsigned char*)g_Bq + i * 16);
    }
    // fused glove column-sum (overlaps B stream-in)
    if (tid < GD) {
        float s = 0.f;
#pragma unroll
        for (int ww = 0; ww < MW; ww++)
            s += glove[(long long)__ldg(&widx[wb + ww]) * GD + tid];
        atomicAdd(&g_gsum[tid], s);
    }
    __syncthreads();

    const uint32_t aoff = (uint32_t)((lane & 15) * ROWB + (lane >> 4) * 16);
    const uint32_t bBase = smb + SM_B + (w * 32 + (lane >> 4) * 8 + (lane & 7)) * ROWB
                         + ((lane >> 3) & 1) * 16;

    float cst[8], hs0 = 0.f, hs1 = 0.f;
#pragma unroll
    for (int i = 0; i < 8; i++) cst[i] = 0.f;

#pragma unroll 1
    for (int t = 0; t < WLEN; t++) {
        const uint32_t aBase = smb + SM_A0 + (t & 1) * ABYTES + aoff;
        const uint32_t aNxt = SM_A0 + ((t & 1) ^ 1) * ABYTES;

        // issue per-char gate loads EARLY (hide under the MMA phase)
        uint32_t cg[2][2][4];   // [m2][h2][a] half2 = (gate e=0, e=1) for col pair
#pragma unroll
        for (int m2 = 0; m2 < 2; m2++)
#pragma unroll
            for (int h2 = 0; h2 < 2; h2++) {
                int m = m2 * 16 + h2 * 8 + r;
                int ch = sm[SM_CI8 + m * WLEN + t];
                const __half* cgr = g_cgq + ch * G4 + w * 32 + q * 2;
#pragma unroll
                for (int a = 0; a < 4; a++)
                    cg[m2][h2][a] = __ldg((const uint32_t*)(cgr + a * 8));
            }

        float acc[2][4][4];
#pragma unroll
        for (int m2 = 0; m2 < 2; m2++)
#pragma unroll
            for (int n = 0; n < 4; n++)
#pragma unroll
                for (int x = 0; x < 4; x++) acc[m2][n][x] = 0.f;

#pragma unroll
        for (int ka = 0; ka < KATOMS; ka++) {
            uint32_t af[2][4], bf[2][4];
            ldsm4(aBase + ka * 32, af[0]);
            ldsm4(aBase + 16 * ROWB + ka * 32, af[1]);
            ldsm4(bBase + ka * 32, bf[0]);
            ldsm4(bBase + 16 * ROWB + ka * 32, bf[1]);
#pragma unroll
            for (int m2 = 0; m2 < 2; m2++)
#pragma unroll
                for (int n = 0; n < 4; n++)
                    mma16816(acc[m2][n], af[m2], &bf[n >> 1][(n & 1) * 2]);
        }

        // epilogue (fp32 tanh.approx, round-11 proven) + cg add + h stores
#pragma unroll
        for (int m2 = 0; m2 < 2; m2++)
#pragma unroll
            for (int h2 = 0; h2 < 2; h2++)
#pragma unroll
                for (int al = 0; al < 2; al++) {
                    float2 cif = __half22float2(*(__half2*)&cg[m2][h2][al]);
                    float2 cgo = __half22float2(*(__half2*)&cg[m2][h2][al + 2]);
                    float iv = acc[m2][al][h2 * 2]     + cif.x;
                    float fv = acc[m2][al][h2 * 2 + 1] + cif.y;
                    float gv = acc[m2][al + 2][h2 * 2]     + cgo.x;
                    float ov = acc[m2][al + 2][h2 * 2 + 1] + cgo.y;
                    int ci = (m2 * 2 + h2) * 2 + al;
                    float ii = fmaf(tanha(0.5f * iv), 0.5f, 0.5f);
                    float ff = fmaf(tanha(0.5f * fv), 0.5f, 0.5f);
                    float gg = tanha(gv);
                    float oo = fmaf(tanha(0.5f * ov), 0.5f, 0.5f);
                    float cn = fmaf(ff, cst[ci], ii * gg);
                    cst[ci] = cn;
                    float hv = oo * tanha(cn);
                    int m = m2 * 16 + h2 * 8 + r;
                    int u = w * 8 + al * 4 + q;
                    *(__half*)(sm + aNxt + m * ROWB + u * 2) = __float2half(hv);
                    if (t == WLEN - 1) { if (al == 0) hs0 += hv; else hs1 += hv; }
                }
        __syncthreads();   // single barrier: RAW for next step + WAR for writes
    }

    // reduce final h over the CTA's 32 words -> g_hsum
#pragma unroll
    for (int off = 4; off < 32; off <<= 1) {
        hs0 += __shfl_xor_sync(0xffffffffu, hs0, off);
        hs1 += __shfl_xor_sync(0xffffffffu, hs1, off);
    }
    if (lane < 4) {
        atomicAdd(&g_hsum[w * 8 + lane], hs0);
        atomicAdd(&g_hsum[w * 8 + 4 + lane], hs1);
    }
}

// ---------------------------------------------------------------------------
// Final: avg -> fc1 + relu -> fc2, parallelized over 8 CTAs (round-9 proven).
// ---------------------------------------------------------------------------
__global__ void final_kernel(const float* __restrict__ fc1_w,
                             const float* __restrict__ fc1_b,
                             const float* __restrict__ fc2_w,
                             const float* __restrict__ fc2_b,
                             float* __restrict__ out) {
    __shared__ float avg[FEAT];
    int tid = threadIdx.x;
    int lane = tid & 31;
    int e = tid & 7;                       // chunk within unit
    int j = blockIdx.x * 64 + (tid >> 3);  // hidden unit

    if (tid < GD) avg[tid] = g_gsum[tid] * (1.f / NW);
    else if (tid < FEAT) avg[tid] = g_hsum[tid - GD] * (1.f / NW);
    __syncthreads();

    int k0 = e * 54;
    int k1 = (k0 + 54 < FEAT) ? k0 + 54 : FEAT;
    const float* wrow = fc1_w + (long long)j * FEAT;
    float p = 0.f;
#pragma unroll 6
    for (int k = k0; k < k1; k++) p = fmaf(wrow[k], avg[k], p);
    p += __shfl_down_sync(0xffffffffu, p, 4, 8);
    p += __shfl_down_sync(0xffffffffu, p, 2, 8);
    p += __shfl_down_sync(0xffffffffu, p, 1, 8);

    float q0 = 0.f, q1 = 0.f;
    if (e == 0) {
        float h = fmaxf(p + fc1_b[j], 0.f);
        q0 = fc2_w[j] * h;
        q1 = fc2_w[HID + j] * h;
    }
#pragma unroll
    for (int off = 16; off >= 8; off >>= 1) {
        q0 += __shfl_down_sync(0xffffffffu, q0, off);
        q1 += __shfl_down_sync(0xffffffffu, q1, off);
    }
    if (lane == 0) {
        atomicAdd(&g_out2[0], q0);
        atomicAdd(&g_out2[1], q1);
    }
    __threadfence();
    __syncthreads();
    if (tid == 0) {
        int old = atomicAdd(&g_t2, 1);
        if (old == 7) {
            out[0] = ldcv(&g_out2[0]) + fc2_b[0];
            out[1] = ldcv(&g_out2[1]) + fc2_b[1];
        }
    }
}

// ---------------------------------------------------------------------------
extern "C" void kernel_launch(void* const* d_in, const int* in_sizes, int n_in,
                              void* d_out, int out_size) {
    const int*   widx  = (const int*)d_in[0];
    const int*   cidx  = (const int*)d_in[1];
    const float* glove = (const float*)d_in[2];
    const float* cemb  = (const float*)d_in[3];
    const float* W_ih  = (const float*)d_in[4];
    const float* W_hh  = (const float*)d_in[5];
    const float* b_ih  = (const float*)d_in[6];
    const float* b_hh  = (const float*)d_in[7];
    const float* fc1_w = (const float*)d_in[8];
    const float* fc1_b = (const float*)d_in[9];
    const float* fc2_w = (const float*)d_in[10];
    const float* fc2_b = (const float*)d_in[11];
    float* out = (float*)d_out;

    cudaFuncSetAttribute(lstm_mma_kernel,
                         cudaFuncAttributeMaxDynamicSharedMemorySize, SM_TOTAL);

    prep_all<<<G4 + CV + 1, 128>>>(W_hh, W_ih, b_ih, b_hh, cemb);
    lstm_mma_kernel<<<NBLK, THR, SM_TOTAL>>>(cidx, widx, glove);
    final_kernel<<<8, 512>>>(fc1_w, fc1_b, fc2_w, fc2_b, out);
}

// round 14
// speedup vs baseline: 1.0904x; 1.0904x over previous
#include <cuda_runtime.h>
#include <cuda_fp16.h>
#include <math.h>
#include <stdint.h>

#define NW     4096
#define WLEN   16
#define GD     300
#define CE     50
#define CH     128
#define G4     512
#define CV     100
#define HID    512
#define FEAT   428

#define MW     32                 // words per CTA (MMA M)
#define THR    512                // 16 warps, each owns 32 gate columns
#define NBLK   (NW / MW)          // 128
#define KEXT   192                // 128 h + 50 emb + 1 bias + 13 pad
#define KATOMS (KEXT / 16)        // 12
#define ROWB   400                // smem row stride bytes (200 halves)
#define ABYTES (MW * ROWB)        // 12800

// ---- smem layout (double-buffered A; total 231040, no static shared) ----
#define SM_CI8   0                          // 32*16 u8 = 512
#define SM_WIDX  512                        // 32*4 = 128
#define SM_A0    640                        // 12800
#define SM_A1    (SM_A0 + ABYTES)           // 13440
#define SM_B     (SM_A1 + ABYTES)           // 26240; 512*400 = 204800
#define SM_TOTAL (SM_B + G4 * ROWB)         // 231040

// ---- device scratch ----
__device__ __align__(16) __half g_Bext[G4 * KEXT];  // permuted fused weights
__device__ __align__(16) __half g_embq[CV * 64];    // [emb(50) | 1 | 0pad] per char
__device__ float g_gsum[GD];
__device__ float g_hsum[CH];
__device__ float g_out2[2];
__device__ int   g_t2 = 0;

// ---- helpers ----
__device__ __forceinline__ uint32_t smem_u32(const void* p) {
    uint32_t a;
    asm("{ .reg .u64 t; cvta.to.shared.u64 t, %1; cvt.u32.u64 %0, t; }" : "=r"(a) : "l"(p));
    return a;
}
__device__ __forceinline__ void ldsm4(uint32_t addr, uint32_t r[4]) {
    asm volatile("ldmatrix.sync.aligned.m8n8.x4.shared.b16 {%0,%1,%2,%3}, [%4];"
        : "=r"(r[0]), "=r"(r[1]), "=r"(r[2]), "=r"(r[3]) : "r"(addr));
}
__device__ __forceinline__ void mma16816(float d[4], const uint32_t a[4], const uint32_t b[2]) {
    asm volatile("mma.sync.aligned.m16n8k16.row.col.f32.f16.f16.f32 "
        "{%0,%1,%2,%3}, {%4,%5,%6,%7}, {%8,%9}, {%0,%1,%2,%3};"
        : "+f"(d[0]), "+f"(d[1]), "+f"(d[2]), "+f"(d[3])
        : "r"(a[0]), "r"(a[1]), "r"(a[2]), "r"(a[3]), "r"(b[0]), "r"(b[1]));
}
__device__ __forceinline__ float tanha(float x) {
    float y; asm("tanh.approx.f32 %0, %1;" : "=f"(y) : "f"(x)); return y;
}
__device__ __forceinline__ float ldcv(const float* p) {
    float v; asm volatile("ld.global.cv.f32 %0, [%1];" : "=f"(v) : "l"(p)); return v;
}

// gate-column permutation: warp w owns cols j = w*32 + c, c = a*8 + q*2 + e
//   gate g = 2*(a>>1) + e ; unit u = w*8 + (a&1)*4 + q

// ---------------------------------------------------------------------------
// Prep (proven 4.8us): blocks 0..511 build g_Bext; 512..611 embq + zeros.
// grid 612 x 96
// ---------------------------------------------------------------------------
__global__ void prep_all(const float* __restrict__ W_hh, const float* __restrict__ W_ih,
                         const float* __restrict__ b_ih, const float* __restrict__ b_hh,
                         const float* __restrict__ char_embed) {
    if (blockIdx.x < G4) {
        int j = blockIdx.x;
        int w = j >> 5, c = j & 31;
        int a = c >> 3, q = (c >> 1) & 3, e = c & 1;
        int g = 2 * (a >> 1) + e;
        int u = w * 8 + (a & 1) * 4 + q;
        int row = g * CH + u;
        int k0 = threadIdx.x * 2;
        float v[2];
#pragma unroll
        for (int d = 0; d < 2; d++) {
            int k = k0 + d;
            float x;
            if (k < CH)            x = W_hh[row * CH + k];
            else if (k < CH + CE)  x = W_ih[row * CE + (k - CH)];
            else if (k == CH + CE) x = b_ih[row] + b_hh[row];
            else                   x = 0.f;
            v[d] = x;
        }
        *(__half2*)(g_Bext + j * KEXT + k0) = __floats2half2_rn(v[0], v[1]);
    } else {
        int cix = blockIdx.x - G4;
        int k = threadIdx.x;
        if (k < 64) {
            float v = (k < CE) ? char_embed[cix * CE + k] : (k == CE ? 1.f : 0.f);
            g_embq[cix * 64 + k] = __float2half(v);
        }
        int z = cix * 96 + threadIdx.x;
        if (z < GD) g_gsum[z] = 0.f;
        if (z < CH) g_hsum[z] = 0.f;
        if (blockIdx.x == G4 && threadIdx.x == 0) {
            g_out2[0] = 0.f; g_out2[1] = 0.f; g_t2 = 0;
        }
    }
}

// ---------------------------------------------------------------------------
// LSTM via mma.sync + fused glove gather; double-buffered A, 1 barrier/step;
// M-halved mainloop to overlap epilogue MUFU with second-half MMA.
// 128 CTAs x 512 thr; M=32 words, N=512 gates, K=192. B_ext smem-resident.
// ---------------------------------------------------------------------------
__global__ void __launch_bounds__(THR, 1) lstm_mma_kernel(const int* __restrict__ cidx,
                                                          const int* __restrict__ widx,
                                                          const float* __restrict__ glove) {
    extern __shared__ unsigned char sm[];
    uint32_t smb = smem_u32(sm);
    int tid = threadIdx.x;
    int w = tid >> 5, lane = tid & 31;
    int q = lane & 3, r = lane >> 2;

    const int wb = blockIdx.x * MW;
    if (tid < MW * WLEN) sm[SM_CI8 + tid] = (unsigned char)cidx[wb * WLEN + tid];
    if (tid < MW) ((int*)(sm + SM_WIDX))[tid] = widx[wb + tid];
    {   // zero A0 h-region (one uint4 per thread: 32 rows x 16 segs)
        int row = tid >> 4, seg = tid & 15;
        *(uint4*)(sm + SM_A0 + row * ROWB + seg * 16) = make_uint4(0, 0, 0, 0);
    }
    for (int i = tid; i < G4 * 24; i += THR) {        // 24 uint4 per 192-half row
        int row = i / 24, s = i % 24;
        *(uint4*)(sm + SM_B + row * ROWB + s * 16) =
            *(const uint4*)((const unsigned char*)g_Bext + i * 16);
    }
    __syncthreads();

    // stage emb for t=0 into A0
    if (tid < 256) {
        int word = tid >> 3, seg = tid & 7;
        int ch = sm[SM_CI8 + word * WLEN];
        *(uint4*)(sm + SM_A0 + word * ROWB + 256 + seg * 16) =
            *(const uint4*)((const unsigned char*)g_embq + ch * 128 + seg * 16);
    }
    // fused glove column-sum for this CTA's 32 words
    if (tid < GD) {
        const int* rows = (const int*)(sm + SM_WIDX);
        float s = 0.f;
#pragma unroll
        for (int ww = 0; ww < MW; ww++)
            s += glove[(long long)rows[ww] * GD + tid];
        atomicAdd(&g_gsum[tid], s);
    }
    __syncthreads();

    const uint32_t aoff = (uint32_t)((lane & 15) * ROWB + (lane >> 4) * 16);
    const uint32_t bBase = smb + SM_B + (w * 32 + (lane >> 4) * 8 + (lane & 7)) * ROWB
                         + ((lane >> 3) & 1) * 16;

    float cst[8], hs0 = 0.f, hs1 = 0.f;
#pragma unroll
    for (int i = 0; i < 8; i++) cst[i] = 0.f;

#pragma unroll 1
    for (int t = 0; t < WLEN; t++) {
        const uint32_t aBase = smb + SM_A0 + (t & 1) * ABYTES + aoff;
        const uint32_t aNxt = SM_A0 + ((t & 1) ^ 1) * ABYTES;

        // ---- two M-halves: MMA(half) then epilogue(half); the second
        //      half's HMMA stream overlaps the first half's MUFU chain ----
#pragma unroll
        for (int m2 = 0; m2 < 2; m2++) {
            float acc[4][4];
#pragma unroll
            for (int n = 0; n < 4; n++)
#pragma unroll
                for (int x = 0; x < 4; x++) acc[n][x] = 0.f;

#pragma unroll
            for (int ka = 0; ka < KATOMS; ka++) {
                uint32_t af[4], bf[2][4];
                ldsm4(aBase + m2 * 16 * ROWB + ka * 32, af);
                ldsm4(bBase + ka * 32, bf[0]);
                ldsm4(bBase + 16 * ROWB + ka * 32, bf[1]);
#pragma unroll
                for (int n = 0; n < 4; n++)
                    mma16816(acc[n], af, &bf[n >> 1][(n & 1) * 2]);
            }

            // epilogue for this half (fp32 tanh.approx, proven numerics)
#pragma unroll
            for (int h2 = 0; h2 < 2; h2++)
#pragma unroll
                for (int al = 0; al < 2; al++) {
                    float iv = acc[al][h2 * 2];
                    float fv = acc[al][h2 * 2 + 1];
                    float gv = acc[al + 2][h2 * 2];
                    float ov = acc[al + 2][h2 * 2 + 1];
                    int ci = (m2 * 2 + h2) * 2 + al;
                    float ii = fmaf(tanha(0.5f * iv), 0.5f, 0.5f);
                    float ff = fmaf(tanha(0.5f * fv), 0.5f, 0.5f);
                    float gg = tanha(gv);
                    float oo = fmaf(tanha(0.5f * ov), 0.5f, 0.5f);
                    float cn = fmaf(ff, cst[ci], ii * gg);
                    cst[ci] = cn;
                    float hv = oo * tanha(cn);
                    int m = m2 * 16 + r + h2 * 8;
                    int u = w * 8 + al * 4 + q;
                    *(__half*)(sm + aNxt + m * ROWB + u * 2) = __float2half(hv);
                    if (t == WLEN - 1) { if (al == 0) hs0 += hv; else hs1 += hv; }
                }
        }

        if (t < WLEN - 1 && tid < 256) {   // stage emb for t+1 into A[next]
            int word = tid >> 3, seg = tid & 7;
            int ch = sm[SM_CI8 + word * WLEN + t + 1];
            *(uint4*)(sm + aNxt + word * ROWB + 256 + seg * 16) =
                *(const uint4*)((const unsigned char*)g_embq + ch * 128 + seg * 16);
        }
        __syncthreads();   // single barrier: RAW for next step + WAR for writes
    }

    // reduce final h over the CTA's 32 words -> g_hsum
#pragma unroll
    for (int off = 4; off < 32; off <<= 1) {
        hs0 += __shfl_xor_sync(0xffffffffu, hs0, off);
        hs1 += __shfl_xor_sync(0xffffffffu, hs1, off);
    }
    if (lane < 4) {
        atomicAdd(&g_hsum[w * 8 + lane], hs0);
        atomicAdd(&g_hsum[w * 8 + 4 + lane], hs1);
    }
}

// ---------------------------------------------------------------------------
// Final: avg -> fc1 + relu -> fc2, parallelized over 8 CTAs (round-9 proven).
// ---------------------------------------------------------------------------
__global__ void final_kernel(const float* __restrict__ fc1_w,
                             const float* __restrict__ fc1_b,
                             const float* __restrict__ fc2_w,
                             const float* __restrict__ fc2_b,
                             float* __restrict__ out) {
    __shared__ float avg[FEAT];
    int tid = threadIdx.x;
    int lane = tid & 31;
    int e = tid & 7;                       // chunk within unit
    int j = blockIdx.x * 64 + (tid >> 3);  // hidden unit

    if (tid < GD) avg[tid] = g_gsum[tid] * (1.f / NW);
    else if (tid < FEAT) avg[tid] = g_hsum[tid - GD] * (1.f / NW);
    __syncthreads();

    int k0 = e * 54;
    int k1 = (k0 + 54 < FEAT) ? k0 + 54 : FEAT;
    const float* wrow = fc1_w + (long long)j * FEAT;
    float p = 0.f;
#pragma unroll 6
    for (int k = k0; k < k1; k++) p = fmaf(wrow[k], avg[k], p);
    p += __shfl_down_sync(0xffffffffu, p, 4, 8);
    p += __shfl_down_sync(0xffffffffu, p, 2, 8);
    p += __shfl_down_sync(0xffffffffu, p, 1, 8);

    float q0 = 0.f, q1 = 0.f;
    if (e == 0) {
        float h = fmaxf(p + fc1_b[j], 0.f);
        q0 = fc2_w[j] * h;
        q1 = fc2_w[HID + j] * h;
    }
#pragma unroll
    for (int off = 16; off >= 8; off >>= 1) {
        q0 += __shfl_down_sync(0xffffffffu, q0, off);
        q1 += __shfl_down_sync(0xffffffffu, q1, off);
    }
    if (lane == 0) {
        atomicAdd(&g_out2[0], q0);
        atomicAdd(&g_out2[1], q1);
    }
    __threadfence();
    __syncthreads();
    if (tid == 0) {
        int old = atomicAdd(&g_t2, 1);
        if (old == 7) {
            out[0] = ldcv(&g_out2[0]) + fc2_b[0];
            out[1] = ldcv(&g_out2[1]) + fc2_b[1];
        }
    }
}

// ---------------------------------------------------------------------------
extern "C" void kernel_launch(void* const* d_in, const int* in_sizes, int n_in,
                              void* d_out, int out_size) {
    const int*   widx  = (const int*)d_in[0];
    const int*   cidx  = (const int*)d_in[1];
    const float* glove = (const float*)d_in[2];
    const float* cemb  = (const float*)d_in[3];
    const float* W_ih  = (const float*)d_in[4];
    const float* W_hh  = (const float*)d_in[5];
    const float* b_ih  = (const float*)d_in[6];
    const float* b_hh  = (const float*)d_in[7];
    const float* fc1_w = (const float*)d_in[8];
    const float* fc1_b = (const float*)d_in[9];
    const float* fc2_w = (const float*)d_in[10];
    const float* fc2_b = (const float*)d_in[11];
    float* out = (float*)d_out;

    cudaFuncSetAttribute(lstm_mma_kernel,
                         cudaFuncAttributeMaxDynamicSharedMemorySize, SM_TOTAL);

    prep_all<<<G4 + CV, 96>>>(W_hh, W_ih, b_ih, b_hh, cemb);
    lstm_mma_kernel<<<NBLK, THR, SM_TOTAL>>>(cidx, widx, glove);
    final_kernel<<<8, 512>>>(fc1_w, fc1_b, fc2_w, fc2_b, out);
}

// round 15
// speedup vs baseline: 1.1646x; 1.0680x over previous
#include <cuda_runtime.h>
#include <cuda_fp16.h>
#include <math.h>
#include <stdint.h>

#define NW     4096
#define WLEN   16
#define GD     300
#define CE     50
#define CH     128
#define G4     512
#define CV     100
#define HID    512
#define FEAT   428

#define MW     32                 // words per CTA (MMA M)
#define THR    512                // 16 warps, each owns 32 gate columns
#define NBLK   (NW / MW)          // 128
#define KEXT   192                // 128 h + 50 emb + 1 bias + 13 pad
#define KATOMS (KEXT / 16)        // 12
#define ROWB   400                // smem row stride bytes (200 halves)
#define ABYTES (MW * ROWB)        // 12800

// ---- smem layout (double-buffered A; total 231040, no static shared) ----
#define SM_CI8   0                          // 32*16 u8 = 512
#define SM_WIDX  512                        // 32*4 = 128
#define SM_A0    640                        // 12800
#define SM_A1    (SM_A0 + ABYTES)           // 13440
#define SM_B     (SM_A1 + ABYTES)           // 26240; 512*400 = 204800
#define SM_TOTAL (SM_B + G4 * ROWB)         // 231040

// ---- device scratch ----
__device__ __align__(16) __half g_Bext[G4 * KEXT];  // permuted fused weights
__device__ __align__(16) __half g_embq[CV * 64];    // [emb(50) | 1 | 0pad] per char
__device__ float g_gsum[GD];
__device__ float g_hsum[CH];
__device__ float g_out2[2];
__device__ int   g_t2 = 0;

// ---- helpers ----
__device__ __forceinline__ uint32_t smem_u32(const void* p) {
    uint32_t a;
    asm("{ .reg .u64 t; cvta.to.shared.u64 t, %1; cvt.u32.u64 %0, t; }" : "=r"(a) : "l"(p));
    return a;
}
__device__ __forceinline__ void ldsm4(uint32_t addr, uint32_t r[4]) {
    asm volatile("ldmatrix.sync.aligned.m8n8.x4.shared.b16 {%0,%1,%2,%3}, [%4];"
        : "=r"(r[0]), "=r"(r[1]), "=r"(r[2]), "=r"(r[3]) : "r"(addr));
}
__device__ __forceinline__ void mma16816(float d[4], const uint32_t a[4], const uint32_t b[2]) {
    asm volatile("mma.sync.aligned.m16n8k16.row.col.f32.f16.f16.f32 "
        "{%0,%1,%2,%3}, {%4,%5,%6,%7}, {%8,%9}, {%0,%1,%2,%3};"
        : "+f"(d[0]), "+f"(d[1]), "+f"(d[2]), "+f"(d[3])
        : "r"(a[0]), "r"(a[1]), "r"(a[2]), "r"(a[3]), "r"(b[0]), "r"(b[1]));
}
__device__ __forceinline__ float tanha(float x) {
    float y; asm("tanh.approx.f32 %0, %1;" : "=f"(y) : "f"(x)); return y;
}
__device__ __forceinline__ float ldcv(const float* p) {
    float v; asm volatile("ld.global.cv.f32 %0, [%1];" : "=f"(v) : "l"(p)); return v;
}

// NEW gate-column permutation (unit-adjacent):
//   warp w owns cols j = w*32 + c, with c = a*8 + d   (a = K-atom = GATE,
//   d = q*2 + e = unit-low bits). gate g = a ; unit u = w*8 + d.
//   => thread (q,r) accumulator acc[a][h2*2+e] = gate a of unit w*8+q*2+e
//   => the two e-slots are ADJACENT units: h store packs into one u32.

// ---------------------------------------------------------------------------
// Prep (proven 4.8us): blocks 0..511 build g_Bext; 512..611 embq + zeros.
// grid 612 x 96
// ---------------------------------------------------------------------------
__global__ void prep_all(const float* __restrict__ W_hh, const float* __restrict__ W_ih,
                         const float* __restrict__ b_ih, const float* __restrict__ b_hh,
                         const float* __restrict__ char_embed) {
    if (blockIdx.x < G4) {
        int j = blockIdx.x;
        int w = j >> 5, c = j & 31;
        int a = c >> 3, d = c & 7;
        int row = a * CH + w * 8 + d;        // gate a, unit w*8+d
        int k0 = threadIdx.x * 2;
        float v[2];
#pragma unroll
        for (int dd = 0; dd < 2; dd++) {
            int k = k0 + dd;
            float x;
            if (k < CH)            x = W_hh[row * CH + k];
            else if (k < CH + CE)  x = W_ih[row * CE + (k - CH)];
            else if (k == CH + CE) x = b_ih[row] + b_hh[row];
            else                   x = 0.f;
            v[dd] = x;
        }
        *(__half2*)(g_Bext + j * KEXT + k0) = __floats2half2_rn(v[0], v[1]);
    } else {
        int cix = blockIdx.x - G4;
        int k = threadIdx.x;
        if (k < 64) {
            float v = (k < CE) ? char_embed[cix * CE + k] : (k == CE ? 1.f : 0.f);
            g_embq[cix * 64 + k] = __float2half(v);
        }
        int z = cix * 96 + threadIdx.x;
        if (z < GD) g_gsum[z] = 0.f;
        if (z < CH) g_hsum[z] = 0.f;
        if (blockIdx.x == G4 && threadIdx.x == 0) {
            g_out2[0] = 0.f; g_out2[1] = 0.f; g_t2 = 0;
        }
    }
}

// ---------------------------------------------------------------------------
// LSTM via mma.sync + fused glove gather; double-buffered A, 1 barrier/step;
// unit-adjacent permutation -> packed u32 h-stores; balanced emb staging.
// 128 CTAs x 512 thr; M=32 words, N=512 gates, K=192. B_ext smem-resident.
// ---------------------------------------------------------------------------
__global__ void __launch_bounds__(THR, 1) lstm_mma_kernel(const int* __restrict__ cidx,
                                                          const int* __restrict__ widx,
                                                          const float* __restrict__ glove) {
    extern __shared__ unsigned char sm[];
    uint32_t smb = smem_u32(sm);
    int tid = threadIdx.x;
    int w = tid >> 5, lane = tid & 31;
    int q = lane & 3, r = lane >> 2;

    const int wb = blockIdx.x * MW;
    if (tid < MW * WLEN) sm[SM_CI8 + tid] = (unsigned char)cidx[wb * WLEN + tid];
    if (tid < MW) ((int*)(sm + SM_WIDX))[tid] = widx[wb + tid];
    {   // zero A0 h-region (one uint4 per thread: 32 rows x 16 segs)
        int row = tid >> 4, seg = tid & 15;
        *(uint4*)(sm + SM_A0 + row * ROWB + seg * 16) = make_uint4(0, 0, 0, 0);
    }
    for (int i = tid; i < G4 * 24; i += THR) {        // 24 uint4 per 192-half row
        int row = i / 24, s = i % 24;
        *(uint4*)(sm + SM_B + row * ROWB + s * 16) =
            *(const uint4*)((const unsigned char*)g_Bext + i * 16);
    }
    __syncthreads();

    // stage emb for t=0 into A0 (balanced: all 512 threads, uint2 each)
    {
        int word = tid >> 4, seg = tid & 15;
        int ch = sm[SM_CI8 + word * WLEN];
        *(uint2*)(sm + SM_A0 + word * ROWB + 256 + seg * 8) =
            *(const uint2*)((const unsigned char*)g_embq + ch * 128 + seg * 8);
    }
    // fused glove column-sum for this CTA's 32 words
    if (tid < GD) {
        const int* rows = (const int*)(sm + SM_WIDX);
        float s = 0.f;
#pragma unroll
        for (int ww = 0; ww < MW; ww++)
            s += glove[(long long)rows[ww] * GD + tid];
        atomicAdd(&g_gsum[tid], s);
    }
    __syncthreads();

    const uint32_t aoff = (uint32_t)((lane & 15) * ROWB + (lane >> 4) * 16);
    const uint32_t bBase = smb + SM_B + (w * 32 + (lane >> 4) * 8 + (lane & 7)) * ROWB
                         + ((lane >> 3) & 1) * 16;

    float cst[8], hs0 = 0.f, hs1 = 0.f;
#pragma unroll
    for (int i = 0; i < 8; i++) cst[i] = 0.f;

#pragma unroll 1
    for (int t = 0; t < WLEN; t++) {
        const uint32_t aBase = smb + SM_A0 + (t & 1) * ABYTES + aoff;
        const uint32_t aNxt = SM_A0 + ((t & 1) ^ 1) * ABYTES;

        float acc[2][4][4];
#pragma unroll
        for (int m2 = 0; m2 < 2; m2++)
#pragma unroll
            for (int n = 0; n < 4; n++)
#pragma unroll
                for (int x = 0; x < 4; x++) acc[m2][n][x] = 0.f;

#pragma unroll
        for (int ka = 0; ka < KATOMS; ka++) {
            uint32_t af[2][4], bf[2][4];
            ldsm4(aBase + ka * 32, af[0]);
            ldsm4(aBase + 16 * ROWB + ka * 32, af[1]);
            ldsm4(bBase + ka * 32, bf[0]);
            ldsm4(bBase + 16 * ROWB + ka * 32, bf[1]);
#pragma unroll
            for (int m2 = 0; m2 < 2; m2++)
#pragma unroll
                for (int n = 0; n < 4; n++)
                    mma16816(acc[m2][n], af[m2], &bf[n >> 1][(n & 1) * 2]);
        }

        // epilogue: gate = atom index (i,f,g,o = acc[0..3]); e-slots are
        // adjacent units -> pack two h values into one u32 store.
#pragma unroll
        for (int m2 = 0; m2 < 2; m2++)
#pragma unroll
            for (int h2 = 0; h2 < 2; h2++) {
                float hv[2];
#pragma unroll
                for (int e = 0; e < 2; e++) {
                    int x = h2 * 2 + e;
                    float iv = acc[m2][0][x];
                    float fv = acc[m2][1][x];
                    float gv = acc[m2][2][x];
                    float ov = acc[m2][3][x];
                    int ci = (m2 * 2 + h2) * 2 + e;
                    float ii = fmaf(tanha(0.5f * iv), 0.5f, 0.5f);
                    float ff = fmaf(tanha(0.5f * fv), 0.5f, 0.5f);
                    float gg = tanha(gv);
                    float oo = fmaf(tanha(0.5f * ov), 0.5f, 0.5f);
                    float cn = fmaf(ff, cst[ci], ii * gg);
                    cst[ci] = cn;
                    hv[e] = oo * tanha(cn);
                }
                int m = m2 * 16 + h2 * 8 + r;
                __half2 p = __floats2half2_rn(hv[0], hv[1]);
                *(uint32_t*)(sm + aNxt + m * ROWB + (w * 8 + q * 2) * 2) =
                    *(uint32_t*)&p;
                if (t == WLEN - 1) { hs0 += hv[0]; hs1 += hv[1]; }
            }

        if (t < WLEN - 1) {   // stage emb for t+1 (balanced uint2 staging)
            int word = tid >> 4, seg = tid & 15;
            int ch = sm[SM_CI8 + word * WLEN + t + 1];
            *(uint2*)(sm + aNxt + word * ROWB + 256 + seg * 8) =
                *(const uint2*)((const unsigned char*)g_embq + ch * 128 + seg * 8);
        }
        __syncthreads();   // single barrier: RAW for next step + WAR for writes
    }

    // reduce final h (units w*8+2q, w*8+2q+1) over the CTA's 32 words
#pragma unroll
    for (int off = 4; off < 32; off <<= 1) {
        hs0 += __shfl_xor_sync(0xffffffffu, hs0, off);
        hs1 += __shfl_xor_sync(0xffffffffu, hs1, off);
    }
    if (lane < 4) {
        atomicAdd(&g_hsum[w * 8 + lane * 2],     hs0);
        atomicAdd(&g_hsum[w * 8 + lane * 2 + 1], hs1);
    }
}

// ---------------------------------------------------------------------------
// Final: avg -> fc1 + relu -> fc2, parallelized over 8 CTAs (round-9 proven).
// ---------------------------------------------------------------------------
__global__ void final_kernel(const float* __restrict__ fc1_w,
                             const float* __restrict__ fc1_b,
                             const float* __restrict__ fc2_w,
                             const float* __restrict__ fc2_b,
                             float* __restrict__ out) {
    __shared__ float avg[FEAT];
    int tid = threadIdx.x;
    int lane = tid & 31;
    int e = tid & 7;                       // chunk within unit
    int j = blockIdx.x * 64 + (tid >> 3);  // hidden unit

    if (tid < GD) avg[tid] = g_gsum[tid] * (1.f / NW);
    else if (tid < FEAT) avg[tid] = g_hsum[tid - GD] * (1.f / NW);
    __syncthreads();

    int k0 = e * 54;
    int k1 = (k0 + 54 < FEAT) ? k0 + 54 : FEAT;
    const float* wrow = fc1_w + (long long)j * FEAT;
    float p = 0.f;
#pragma unroll 6
    for (int k = k0; k < k1; k++) p = fmaf(wrow[k], avg[k], p);
    p += __shfl_down_sync(0xffffffffu, p, 4, 8);
    p += __shfl_down_sync(0xffffffffu, p, 2, 8);
    p += __shfl_down_sync(0xffffffffu, p, 1, 8);

    float q0 = 0.f, q1 = 0.f;
    if (e == 0) {
        float h = fmaxf(p + fc1_b[j], 0.f);
        q0 = fc2_w[j] * h;
        q1 = fc2_w[HID + j] * h;
    }
#pragma unroll
    for (int off = 16; off >= 8; off >>= 1) {
        q0 += __shfl_down_sync(0xffffffffu, q0, off);
        q1 += __shfl_down_sync(0xffffffffu, q1, off);
    }
    if (lane == 0) {
        atomicAdd(&g_out2[0], q0);
        atomicAdd(&g_out2[1], q1);
    }
    __threadfence();
    __syncthreads();
    if (tid == 0) {
        int old = atomicAdd(&g_t2, 1);
        if (old == 7) {
            out[0] = ldcv(&g_out2[0]) + fc2_b[0];
            out[1] = ldcv(&g_out2[1]) + fc2_b[1];
        }
    }
}

// ---------------------------------------------------------------------------
extern "C" void kernel_launch(void* const* d_in, const int* in_sizes, int n_in,
                              void* d_out, int out_size) {
    const int*   widx  = (const int*)d_in[0];
    const int*   cidx  = (const int*)d_in[1];
    const float* glove = (const float*)d_in[2];
    const float* cemb  = (const float*)d_in[3];
    const float* W_ih  = (const float*)d_in[4];
    const float* W_hh  = (const float*)d_in[5];
    const float* b_ih  = (const float*)d_in[6];
    const float* b_hh  = (const float*)d_in[7];
    const float* fc1_w = (const float*)d_in[8];
    const float* fc1_b = (const float*)d_in[9];
    const float* fc2_w = (const float*)d_in[10];
    const float* fc2_b = (const float*)d_in[11];
    float* out = (float*)d_out;

    cudaFuncSetAttribute(lstm_mma_kernel,
                         cudaFuncAttributeMaxDynamicSharedMemorySize, SM_TOTAL);

    prep_all<<<G4 + CV, 96>>>(W_hh, W_ih, b_ih, b_hh, cemb);
    lstm_mma_kernel<<<NBLK, THR, SM_TOTAL>>>(cidx, widx, glove);
    final_kernel<<<8, 512>>>(fc1_w, fc1_b, fc2_w, fc2_b, out);
}